// round 16
// baseline (speedup 1.0000x reference)
#include <cuda_runtime.h>
#include <math.h>

#define NN 200000
#define NE 5000000
#define NEP (NE + 4 * NN)           // padded edge capacity
#define NBLK ((NN + 1023) / 1024)   // scan blocks (196)

// ---- scratch ----------------------------------------------------------------
__device__ int    g_cnt[NN];       // in-degree (without self-loop)
__device__ int    g_rowptr[NN];    // padded CSR row start (multiple of 4)
__device__ int    g_woff[NN];      // fill cursor
__device__ float  g_dis[NN];
__device__ volatile int g_bagg[NBLK];   // decoupled-lookback: tile aggregate
__device__ volatile int g_bpfx[NBLK];   // inclusive prefix
__device__ volatile int g_bflag[NBLK];  // 0=none, 1=agg ready, 2=prefix ready
__device__ __align__(16) int g_esrc[NEP];  // src ids by dst, rows padded to 4 with sentinel NN
__device__ float  g_A[(NN + 1) * 16];  // Y ping; row NN = zero sentinel
__device__ float  g_B[(NN + 1) * 16];  // Y pong

// ---- zero: counters, lookback flags, sentinels ------------------------------
__global__ void zero_cnt_kernel() {
    int i = blockIdx.x * blockDim.x + threadIdx.x;
    if (i < NN) g_cnt[i] = 0;
    if (i < NBLK) g_bflag[i] = 0;
    // sentinels: A 16-wide, B 16-wide, B 8-wide (A 8-wide is zeroed in fused2)
    int j = i - NBLK;
    if (j >= 0 && j < 16) g_A[NN * 16 + j] = 0.0f;
    else if (j >= 16 && j < 32) g_B[NN * 16 + (j - 16)] = 0.0f;
    else if (j >= 32 && j < 40) g_B[NN * 8 + (j - 32)] = 0.0f;
}

// ---- degree (int4-vectorized edge reads; NE % 4 == 0) -----------------------
__global__ void count_deg_kernel(const int* __restrict__ ei) {
    int q = blockIdx.x * blockDim.x + threadIdx.x;
    if (q >= NE / 4) return;
    int4 d = ((const int4*)(ei + NE))[q];
    if ((unsigned)d.x < NN) atomicAdd(&g_cnt[d.x], 1);
    if ((unsigned)d.y < NN) atomicAdd(&g_cnt[d.y], 1);
    if ((unsigned)d.z < NN) atomicAdd(&g_cnt[d.z], 1);
    if ((unsigned)d.w < NN) atomicAdd(&g_cnt[d.w], 1);
}

// ---- single-pass scan (decoupled lookback) + dis ----------------------------
// exclusive prefix of padded counts -> g_rowptr/g_woff; also g_dis.
__global__ void scan_kernel() {
    __shared__ int s[1024];
    __shared__ int s_pre;
    int b = blockIdx.x;
    int gid = b * 1024 + threadIdx.x;

    int raw = (gid < NN) ? g_cnt[gid] : 0;
    if (gid < NN) g_dis[gid] = rsqrtf((float)(raw + 1));   // self-loop included
    int v = (gid < NN) ? ((raw + 3) & ~3) : 0;             // padded count
    s[threadIdx.x] = v;
    __syncthreads();
    for (int off = 1; off < 1024; off <<= 1) {
        int t = (threadIdx.x >= off) ? s[threadIdx.x - off] : 0;
        __syncthreads();
        s[threadIdx.x] += t;
        __syncthreads();
    }
    int total = s[1023];

    if (threadIdx.x == 0) {
        if (b == 0) {
            g_bpfx[0] = total;
            __threadfence();
            g_bflag[0] = 2;
            s_pre = 0;
        } else {
            g_bagg[b] = total;
            __threadfence();
            g_bflag[b] = 1;
            int run = 0;
            int i = b - 1;
            while (true) {
                int f = g_bflag[i];            // volatile
                if (f == 2) { run += g_bpfx[i]; break; }
                if (f == 1) { run += g_bagg[i]; if (--i < 0) break; }
                // f == 0: spin (predecessors are co-resident; 196 blocks fit)
            }
            g_bpfx[b] = run + total;
            __threadfence();
            g_bflag[b] = 2;
            s_pre = run;
        }
    }
    __syncthreads();
    if (gid < NN) {
        int r = s_pre + s[threadIdx.x] - v;    // global exclusive prefix
        g_rowptr[gid] = r;
        g_woff[gid] = r;
    }
}

// ---- CSR fill (int4-vectorized edge reads) ----------------------------------
__global__ void fill_csr_kernel(const int* __restrict__ ei) {
    int q = blockIdx.x * blockDim.x + threadIdx.x;
    if (q >= NE / 4) return;
    int4 s = ((const int4*)ei)[q];
    int4 d = ((const int4*)(ei + NE))[q];
    if ((unsigned)s.x < NN && (unsigned)d.x < NN) g_esrc[atomicAdd(&g_woff[d.x], 1)] = s.x;
    if ((unsigned)s.y < NN && (unsigned)d.y < NN) g_esrc[atomicAdd(&g_woff[d.y], 1)] = s.y;
    if ((unsigned)s.z < NN && (unsigned)d.z < NN) g_esrc[atomicAdd(&g_woff[d.z], 1)] = s.z;
    if ((unsigned)s.w < NN && (unsigned)d.w < NN) g_esrc[atomicAdd(&g_woff[d.w], 1)] = s.w;
}

// ---- lin1 + pad: pad row tails with sentinel, Y1 = dis*x (12->16 pad) -> A --
__global__ void lin1_pad_kernel(const float* __restrict__ in) {
    int i = blockIdx.x * blockDim.x + threadIdx.x;
    if (i >= NN) return;

    // pad this node's CSR row to a multiple of 4 with the sentinel
    int end = g_rowptr[i] + ((g_cnt[i] + 3) & ~3);
    for (int p = g_woff[i]; p < end; p++) g_esrc[p] = NN;

    float dv = g_dis[i];
    const float4* ip = (const float4*)(in + (size_t)i * 12);
    float4* yp = (float4*)(g_A + (size_t)i * 16);
#pragma unroll
    for (int c = 0; c < 3; c++) {
        float4 v = ip[c];
        v.x *= dv; v.y *= dv; v.z *= dv; v.w *= dv;
        yp[c] = v;
    }
    yp[3] = make_float4(0.0f, 0.0f, 0.0f, 0.0f);   // pad
}

// ---- edge aggregation of one 4-feature chunk (int4 edge ids, padded rows) ---
template <int C>
__device__ __forceinline__ float4 aggregate_chunk(const float4* __restrict__ Xc,
                                                  int i, int c) {
    int beg = g_rowptr[i];                     // multiple of 4
    int pn = (g_cnt[i] + 3) & ~3;              // padded count
    float4 acc = Xc[(size_t)i * C + c];        // self term (dis-prescaled)

    const int4* ep4 = (const int4*)(g_esrc + beg);
    int nq = pn >> 2;
    int k = 0;
    for (; k + 2 <= nq; k += 2) {
        int4 q0 = ep4[k];
        int4 q1 = ep4[k + 1];
        float4 v0 = Xc[(size_t)q0.x * C + c];
        float4 v1 = Xc[(size_t)q0.y * C + c];
        float4 v2 = Xc[(size_t)q0.z * C + c];
        float4 v3 = Xc[(size_t)q0.w * C + c];
        float4 v4 = Xc[(size_t)q1.x * C + c];
        float4 v5 = Xc[(size_t)q1.y * C + c];
        float4 v6 = Xc[(size_t)q1.z * C + c];
        float4 v7 = Xc[(size_t)q1.w * C + c];
        acc.x += ((v0.x + v1.x) + (v2.x + v3.x)) + ((v4.x + v5.x) + (v6.x + v7.x));
        acc.y += ((v0.y + v1.y) + (v2.y + v3.y)) + ((v4.y + v5.y) + (v6.y + v7.y));
        acc.z += ((v0.z + v1.z) + (v2.z + v3.z)) + ((v4.z + v5.z) + (v6.z + v7.z));
        acc.w += ((v0.w + v1.w) + (v2.w + v3.w)) + ((v4.w + v5.w) + (v6.w + v7.w));
    }
    if (k < nq) {
        int4 q0 = ep4[k];
        float4 v0 = Xc[(size_t)q0.x * C + c];
        float4 v1 = Xc[(size_t)q0.y * C + c];
        float4 v2 = Xc[(size_t)q0.z * C + c];
        float4 v3 = Xc[(size_t)q0.w * C + c];
        acc.x += (v0.x + v1.x) + (v2.x + v3.x);
        acc.y += (v0.y + v1.y) + (v2.y + v3.y);
        acc.z += (v0.z + v1.z) + (v2.z + v3.z);
        acc.w += (v0.w + v1.w) + (v2.w + v3.w);
    }
    return acc;
}

// ---- fused1: gather Y1 (A, 16-wide, 12 valid) -> @W1 +b1 relu -> @W2 ->
//      Y2 = dis*(h1@W2) (B, 8-wide). C=4 lanes/node, FPL=2.
__global__ void fused1_kernel(const float* __restrict__ W1, const float* __restrict__ b1,
                              const float* __restrict__ W2) {
    __shared__ float sW1[12 * 16];
    __shared__ float sW2[16 * 8];
    __shared__ float sb1[16];
    int t = threadIdx.x;
    if (t < 192) sW1[t] = W1[t];
    if (t < 128) sW2[t] = W2[t];
    if (t < 16) sb1[t] = b1[t];
    __syncthreads();

    int idx = blockIdx.x * blockDim.x + t;
    if (idx >= NN * 4) return;    // whole-warp exits
    int i = idx >> 2;
    int c = idx & 3;

    float4 acc;
    if (c == 3) acc = make_float4(0.0f, 0.0f, 0.0f, 0.0f);  // pad chunk, known zero
    else acc = aggregate_chunk<4>((const float4*)g_A, i, c);
    float dv = g_dis[i];

    // butterfly: assemble 12 valid features (chunk 3 is pad)
    float row[12];
    if (c < 3) { row[4*c] = acc.x; row[4*c+1] = acc.y; row[4*c+2] = acc.z; row[4*c+3] = acc.w; }
#pragma unroll
    for (int j = 1; j < 4; j++) {
        int cc = c ^ j;
        float rx = __shfl_xor_sync(0xffffffffu, acc.x, j);
        float ry = __shfl_xor_sync(0xffffffffu, acc.y, j);
        float rz = __shfl_xor_sync(0xffffffffu, acc.z, j);
        float rw = __shfl_xor_sync(0xffffffffu, acc.w, j);
        if (cc < 3) { row[4*cc] = rx; row[4*cc+1] = ry; row[4*cc+2] = rz; row[4*cc+3] = rw; }
    }

    // h1 = relu( (dv*row) @ W1 + b1 )
    float h1[16];
#pragma unroll
    for (int f = 0; f < 16; f++) h1[f] = sb1[f];
#pragma unroll
    for (int k = 0; k < 12; k++) {
        float a = dv * row[k];
#pragma unroll
        for (int f = 0; f < 16; f++) h1[f] = fmaf(a, sW1[k * 16 + f], h1[f]);
    }
#pragma unroll
    for (int f = 0; f < 16; f++) h1[f] = fmaxf(h1[f], 0.0f);

    // this lane's 2 output columns of W2; Y2 = dv * (h1 @ W2)
    float o0 = 0.0f, o1 = 0.0f;
#pragma unroll
    for (int k = 0; k < 16; k++) {
        o0 = fmaf(h1[k], sW2[k * 8 + 2 * c + 0], o0);
        o1 = fmaf(h1[k], sW2[k * 8 + 2 * c + 1], o1);
    }
    float* op = g_B + (size_t)i * 8 + 2 * c;
    op[0] = o0 * dv;
    op[1] = o1 * dv;
}

// ---- fused2: gather Y2 (B, 8-wide) -> Y3 = dis*(dis*agg + b2) (A, 8-wide) ---
__global__ void fused2_kernel(const float* __restrict__ b2) {
    int idx = blockIdx.x * blockDim.x + threadIdx.x;
    if (idx == 0) {   // zero A 8-wide sentinel (Y1 in A is dead now)
        float4 z = make_float4(0.0f, 0.0f, 0.0f, 0.0f);
        ((float4*)(g_A + NN * 8))[0] = z;
        ((float4*)(g_A + NN * 8))[1] = z;
    }
    if (idx >= NN * 2) return;
    int i = idx >> 1;
    int c = idx & 1;

    float4 acc = aggregate_chunk<2>((const float4*)g_B, i, c);
    float dv = g_dis[i];
    float4 r;
    r.x = dv * fmaf(dv, acc.x, b2[4 * c + 0]);
    r.y = dv * fmaf(dv, acc.y, b2[4 * c + 1]);
    r.z = dv * fmaf(dv, acc.z, b2[4 * c + 2]);
    r.w = dv * fmaf(dv, acc.w, b2[4 * c + 3]);
    ((float4*)(g_A + (size_t)i * 8))[c] = r;
}

// ---- fused3: gather Y3 (A, 8-wide) -> @W3 +b3 relu -> @W4 ->
//      Y4 = dis*(h3@W4) (B, 16-wide, 12 valid + 4 pad). C=2, 6 cols/lane.
__global__ void fused3_kernel(const float* __restrict__ W3, const float* __restrict__ b3,
                              const float* __restrict__ W4) {
    __shared__ float sW3[8 * 16];
    __shared__ float sW4[16 * 12];
    __shared__ float sb3[16];
    int t = threadIdx.x;
    if (t < 128) sW3[t] = W3[t];
    if (t < 192) sW4[t] = W4[t];
    if (t < 16) sb3[t] = b3[t];
    __syncthreads();

    int idx = blockIdx.x * blockDim.x + t;
    if (idx >= NN * 2) return;
    int i = idx >> 1;
    int c = idx & 1;

    float4 acc = aggregate_chunk<2>((const float4*)g_A, i, c);
    float dv = g_dis[i];

    float row[8];
    row[4*c] = acc.x; row[4*c+1] = acc.y; row[4*c+2] = acc.z; row[4*c+3] = acc.w;
    {
        int cc = c ^ 1;
        row[4*cc]   = __shfl_xor_sync(0xffffffffu, acc.x, 1);
        row[4*cc+1] = __shfl_xor_sync(0xffffffffu, acc.y, 1);
        row[4*cc+2] = __shfl_xor_sync(0xffffffffu, acc.z, 1);
        row[4*cc+3] = __shfl_xor_sync(0xffffffffu, acc.w, 1);
    }

    float h3[16];
#pragma unroll
    for (int f = 0; f < 16; f++) h3[f] = sb3[f];
#pragma unroll
    for (int k = 0; k < 8; k++) {
        float a = dv * row[k];
#pragma unroll
        for (int f = 0; f < 16; f++) h3[f] = fmaf(a, sW3[k * 16 + f], h3[f]);
    }
#pragma unroll
    for (int f = 0; f < 16; f++) h3[f] = fmaxf(h3[f], 0.0f);

    float o[6];
#pragma unroll
    for (int f = 0; f < 6; f++) o[f] = 0.0f;
#pragma unroll
    for (int k = 0; k < 16; k++)
#pragma unroll
        for (int f = 0; f < 6; f++)
            o[f] = fmaf(h3[k], sW4[k * 12 + 6 * c + f], o[f]);

    float* op = g_B + (size_t)i * 16 + 6 * c;
#pragma unroll
    for (int f = 0; f < 6; f++) op[f] = o[f] * dv;
    if (c == 1) {   // pad cols 12..15
        float* pp = g_B + (size_t)i * 16 + 12;
        pp[0] = 0.0f; pp[1] = 0.0f; pp[2] = 0.0f; pp[3] = 0.0f;
    }
}

// ---- final: gather Y4 (B, 16-wide stride, 12 valid) -> sigmoid -> out -------
// NN*3 threads (no idle pad lanes; no shuffles needed).
__global__ void final_kernel(float4* __restrict__ out, const float* __restrict__ b4) {
    int idx = blockIdx.x * blockDim.x + threadIdx.x;
    if (idx >= NN * 3) return;
    int i = idx / 3;
    int c = idx - i * 3;

    float4 acc = aggregate_chunk<4>((const float4*)g_B, i, c);   // stride 4, chunk c<3
    float dv = g_dis[i];

    float4 r;
    r.x = 1.0f / (1.0f + expf(-fmaf(dv, acc.x, b4[4 * c + 0])));
    r.y = 1.0f / (1.0f + expf(-fmaf(dv, acc.y, b4[4 * c + 1])));
    r.z = 1.0f / (1.0f + expf(-fmaf(dv, acc.z, b4[4 * c + 2])));
    r.w = 1.0f / (1.0f + expf(-fmaf(dv, acc.w, b4[4 * c + 3])));
    out[idx] = r;
}

// ---- launch -----------------------------------------------------------------
extern "C" void kernel_launch(void* const* d_in, const int* in_sizes, int n_in,
                              void* d_out, int out_size) {
    const float* x  = (const float*)d_in[0];
    const int*   ei = (const int*)d_in[1];   // int32 edge_index [2, E]
    const float* W1 = (const float*)d_in[2]; const float* b1 = (const float*)d_in[3];
    const float* W2 = (const float*)d_in[4]; const float* b2 = (const float*)d_in[5];
    const float* W3 = (const float*)d_in[6]; const float* b3 = (const float*)d_in[7];
    const float* W4 = (const float*)d_in[8]; const float* b4 = (const float*)d_in[9];
    float* out = (float*)d_out;

    const int BT = 256;
    const int gN  = (NN + BT - 1) / BT;
    const int gE4 = (NE / 4 + BT - 1) / BT;
    const int g2  = (NN * 2 + BT - 1) / BT;
    const int g3  = (NN * 3 + BT - 1) / BT;
    const int g4  = (NN * 4 + BT - 1) / BT;

    zero_cnt_kernel<<<gN, BT>>>();
    count_deg_kernel<<<gE4, BT>>>(ei);
    scan_kernel<<<NBLK, 1024>>>();           // rowptr/woff + dis, single pass
    fill_csr_kernel<<<gE4, BT>>>(ei);
    lin1_pad_kernel<<<gN, BT>>>(x);          // pad tails + Y1 = dis*x -> A

    fused1_kernel<<<g4, BT>>>(W1, b1, W2);   // -> Y2 (B, 8)
    fused2_kernel<<<g2, BT>>>(b2);           // -> Y3 (A, 8)
    fused3_kernel<<<g2, BT>>>(W3, b3, W4);   // -> Y4 (B, 16 padded)
    final_kernel<<<g3, BT>>>((float4*)out, b4);
}

// round 17
// speedup vs baseline: 1.0020x; 1.0020x over previous
#include <cuda_runtime.h>
#include <math.h>

#define NN 200000
#define NE 5000000
#define NEP (NE + 4 * NN)           // padded edge capacity
#define NBLK ((NN + 1023) / 1024)   // scan blocks (196)

// ---- scratch ----------------------------------------------------------------
__device__ int    g_cnt[NN];       // in-degree (without self-loop)
__device__ int    g_rowptr[NN];    // padded CSR row start (multiple of 4)
__device__ int    g_woff[NN];      // fill cursor
__device__ float  g_dis[NN];
__device__ volatile int g_bagg[NBLK];   // decoupled-lookback: tile aggregate
__device__ volatile int g_bpfx[NBLK];   // inclusive prefix
__device__ volatile int g_bflag[NBLK];  // 0=none, 1=agg ready, 2=prefix ready
__device__ __align__(16) int g_esrc[NEP];  // src ids by dst, rows padded to 4 with sentinel NN
__device__ float  g_A[(NN + 1) * 16];  // Y ping; row NN = zero sentinel
__device__ float  g_B[(NN + 1) * 16];  // Y pong

// ---- zero: counters, lookback flags, sentinels ------------------------------
__global__ void zero_cnt_kernel() {
    int i = blockIdx.x * blockDim.x + threadIdx.x;
    if (i < NN) g_cnt[i] = 0;
    if (i < NBLK) g_bflag[i] = 0;
    // sentinels: A 16-wide, B 16-wide, B 8-wide (A 8-wide is zeroed in fused2)
    int j = i - NBLK;
    if (j >= 0 && j < 16) g_A[NN * 16 + j] = 0.0f;
    else if (j >= 16 && j < 32) g_B[NN * 16 + (j - 16)] = 0.0f;
    else if (j >= 32 && j < 40) g_B[NN * 8 + (j - 32)] = 0.0f;
}

// ---- degree (scalar: one edge per thread, max warp-level MLP) ---------------
__global__ void count_deg_kernel(const int* __restrict__ ei) {
    int e = blockIdx.x * blockDim.x + threadIdx.x;
    if (e < NE) {
        int d = ei[NE + e];
        if ((unsigned)d < NN) atomicAdd(&g_cnt[d], 1);
    }
}

// ---- single-pass scan (decoupled lookback) + dis ----------------------------
__global__ void scan_kernel() {
    __shared__ int s[1024];
    __shared__ int s_pre;
    int b = blockIdx.x;
    int gid = b * 1024 + threadIdx.x;

    int raw = (gid < NN) ? g_cnt[gid] : 0;
    if (gid < NN) g_dis[gid] = rsqrtf((float)(raw + 1));   // self-loop included
    int v = (gid < NN) ? ((raw + 3) & ~3) : 0;             // padded count
    s[threadIdx.x] = v;
    __syncthreads();
    for (int off = 1; off < 1024; off <<= 1) {
        int t = (threadIdx.x >= off) ? s[threadIdx.x - off] : 0;
        __syncthreads();
        s[threadIdx.x] += t;
        __syncthreads();
    }
    int total = s[1023];

    if (threadIdx.x == 0) {
        if (b == 0) {
            g_bpfx[0] = total;
            __threadfence();
            g_bflag[0] = 2;
            s_pre = 0;
        } else {
            g_bagg[b] = total;
            __threadfence();
            g_bflag[b] = 1;
            int run = 0;
            int i = b - 1;
            while (true) {
                int f = g_bflag[i];            // volatile
                if (f == 2) { run += g_bpfx[i]; break; }
                if (f == 1) { run += g_bagg[i]; if (--i < 0) break; }
                // f == 0: spin (all 196 blocks co-resident)
            }
            g_bpfx[b] = run + total;
            __threadfence();
            g_bflag[b] = 2;
            s_pre = run;
        }
    }
    __syncthreads();
    if (gid < NN) {
        int r = s_pre + s[threadIdx.x] - v;    // global exclusive prefix
        g_rowptr[gid] = r;
        g_woff[gid] = r;
    }
}

// ---- CSR fill (scalar: one edge per thread) ---------------------------------
__global__ void fill_csr_kernel(const int* __restrict__ ei) {
    int e = blockIdx.x * blockDim.x + threadIdx.x;
    if (e >= NE) return;
    int s = ei[e];
    int d = ei[NE + e];
    if ((unsigned)s >= NN || (unsigned)d >= NN) return;  // trap-proof guard
    int pos = atomicAdd(&g_woff[d], 1);
    g_esrc[pos] = s;
}

// ---- lin1 + pad: pad row tails with sentinel, Y1 = dis*x (12->16 pad) -> A --
__global__ void lin1_pad_kernel(const float* __restrict__ in) {
    int i = blockIdx.x * blockDim.x + threadIdx.x;
    if (i >= NN) return;

    int end = g_rowptr[i] + ((g_cnt[i] + 3) & ~3);
    for (int p = g_woff[i]; p < end; p++) g_esrc[p] = NN;  // sentinel

    float dv = g_dis[i];
    const float4* ip = (const float4*)(in + (size_t)i * 12);
    float4* yp = (float4*)(g_A + (size_t)i * 16);
#pragma unroll
    for (int c = 0; c < 3; c++) {
        float4 v = ip[c];
        v.x *= dv; v.y *= dv; v.z *= dv; v.w *= dv;
        yp[c] = v;
    }
    yp[3] = make_float4(0.0f, 0.0f, 0.0f, 0.0f);   // pad
}

// ---- edge aggregation of one 4-feature chunk (int4 edge ids, padded rows) ---
template <int C>
__device__ __forceinline__ float4 aggregate_chunk(const float4* __restrict__ Xc,
                                                  int i, int c) {
    int beg = g_rowptr[i];                     // multiple of 4
    int pn = (g_cnt[i] + 3) & ~3;              // padded count
    float4 acc = Xc[(size_t)i * C + c];        // self term (dis-prescaled)

    const int4* ep4 = (const int4*)(g_esrc + beg);
    int nq = pn >> 2;
    int k = 0;
    for (; k + 2 <= nq; k += 2) {
        int4 q0 = ep4[k];
        int4 q1 = ep4[k + 1];
        float4 v0 = Xc[(size_t)q0.x * C + c];
        float4 v1 = Xc[(size_t)q0.y * C + c];
        float4 v2 = Xc[(size_t)q0.z * C + c];
        float4 v3 = Xc[(size_t)q0.w * C + c];
        float4 v4 = Xc[(size_t)q1.x * C + c];
        float4 v5 = Xc[(size_t)q1.y * C + c];
        float4 v6 = Xc[(size_t)q1.z * C + c];
        float4 v7 = Xc[(size_t)q1.w * C + c];
        acc.x += ((v0.x + v1.x) + (v2.x + v3.x)) + ((v4.x + v5.x) + (v6.x + v7.x));
        acc.y += ((v0.y + v1.y) + (v2.y + v3.y)) + ((v4.y + v5.y) + (v6.y + v7.y));
        acc.z += ((v0.z + v1.z) + (v2.z + v3.z)) + ((v4.z + v5.z) + (v6.z + v7.z));
        acc.w += ((v0.w + v1.w) + (v2.w + v3.w)) + ((v4.w + v5.w) + (v6.w + v7.w));
    }
    if (k < nq) {
        int4 q0 = ep4[k];
        float4 v0 = Xc[(size_t)q0.x * C + c];
        float4 v1 = Xc[(size_t)q0.y * C + c];
        float4 v2 = Xc[(size_t)q0.z * C + c];
        float4 v3 = Xc[(size_t)q0.w * C + c];
        acc.x += (v0.x + v1.x) + (v2.x + v3.x);
        acc.y += (v0.y + v1.y) + (v2.y + v3.y);
        acc.z += (v0.z + v1.z) + (v2.z + v3.z);
        acc.w += (v0.w + v1.w) + (v2.w + v3.w);
    }
    return acc;
}

// ---- fused1: gather Y1 (A, 16-wide, 12 valid) -> @W1 +b1 relu -> @W2 ->
//      Y2 = dis*(h1@W2) (B, 8-wide). C=4 lanes/node, FPL=2.
__global__ void fused1_kernel(const float* __restrict__ W1, const float* __restrict__ b1,
                              const float* __restrict__ W2) {
    __shared__ float sW1[12 * 16];
    __shared__ float sW2[16 * 8];
    __shared__ float sb1[16];
    int t = threadIdx.x;
    if (t < 192) sW1[t] = W1[t];
    if (t < 128) sW2[t] = W2[t];
    if (t < 16) sb1[t] = b1[t];
    __syncthreads();

    int idx = blockIdx.x * blockDim.x + t;
    if (idx >= NN * 4) return;    // whole-warp exits
    int i = idx >> 2;
    int c = idx & 3;

    float4 acc;
    if (c == 3) acc = make_float4(0.0f, 0.0f, 0.0f, 0.0f);  // pad chunk, known zero
    else acc = aggregate_chunk<4>((const float4*)g_A, i, c);
    float dv = g_dis[i];

    float row[12];
    if (c < 3) { row[4*c] = acc.x; row[4*c+1] = acc.y; row[4*c+2] = acc.z; row[4*c+3] = acc.w; }
#pragma unroll
    for (int j = 1; j < 4; j++) {
        int cc = c ^ j;
        float rx = __shfl_xor_sync(0xffffffffu, acc.x, j);
        float ry = __shfl_xor_sync(0xffffffffu, acc.y, j);
        float rz = __shfl_xor_sync(0xffffffffu, acc.z, j);
        float rw = __shfl_xor_sync(0xffffffffu, acc.w, j);
        if (cc < 3) { row[4*cc] = rx; row[4*cc+1] = ry; row[4*cc+2] = rz; row[4*cc+3] = rw; }
    }

    float h1[16];
#pragma unroll
    for (int f = 0; f < 16; f++) h1[f] = sb1[f];
#pragma unroll
    for (int k = 0; k < 12; k++) {
        float a = dv * row[k];
#pragma unroll
        for (int f = 0; f < 16; f++) h1[f] = fmaf(a, sW1[k * 16 + f], h1[f]);
    }
#pragma unroll
    for (int f = 0; f < 16; f++) h1[f] = fmaxf(h1[f], 0.0f);

    float o0 = 0.0f, o1 = 0.0f;
#pragma unroll
    for (int k = 0; k < 16; k++) {
        o0 = fmaf(h1[k], sW2[k * 8 + 2 * c + 0], o0);
        o1 = fmaf(h1[k], sW2[k * 8 + 2 * c + 1], o1);
    }
    float* op = g_B + (size_t)i * 8 + 2 * c;
    op[0] = o0 * dv;
    op[1] = o1 * dv;
}

// ---- fused2: gather Y2 (B, 8-wide) -> Y3 = dis*(dis*agg + b2) (A, 8-wide) ---
__global__ void fused2_kernel(const float* __restrict__ b2) {
    int idx = blockIdx.x * blockDim.x + threadIdx.x;
    if (idx == 0) {   // zero A 8-wide sentinel
        float4 z = make_float4(0.0f, 0.0f, 0.0f, 0.0f);
        ((float4*)(g_A + NN * 8))[0] = z;
        ((float4*)(g_A + NN * 8))[1] = z;
    }
    if (idx >= NN * 2) return;
    int i = idx >> 1;
    int c = idx & 1;

    float4 acc = aggregate_chunk<2>((const float4*)g_B, i, c);
    float dv = g_dis[i];
    float4 r;
    r.x = dv * fmaf(dv, acc.x, b2[4 * c + 0]);
    r.y = dv * fmaf(dv, acc.y, b2[4 * c + 1]);
    r.z = dv * fmaf(dv, acc.z, b2[4 * c + 2]);
    r.w = dv * fmaf(dv, acc.w, b2[4 * c + 3]);
    ((float4*)(g_A + (size_t)i * 8))[c] = r;
}

// ---- fused3: gather Y3 (A, 8-wide) -> @W3 +b3 relu -> @W4 ->
//      Y4 = dis*(h3@W4) (B, 16-wide, 12 valid + 4 pad). C=2, 6 cols/lane.
__global__ void fused3_kernel(const float* __restrict__ W3, const float* __restrict__ b3,
                              const float* __restrict__ W4) {
    __shared__ float sW3[8 * 16];
    __shared__ float sW4[16 * 12];
    __shared__ float sb3[16];
    int t = threadIdx.x;
    if (t < 128) sW3[t] = W3[t];
    if (t < 192) sW4[t] = W4[t];
    if (t < 16) sb3[t] = b3[t];
    __syncthreads();

    int idx = blockIdx.x * blockDim.x + t;
    if (idx >= NN * 2) return;
    int i = idx >> 1;
    int c = idx & 1;

    float4 acc = aggregate_chunk<2>((const float4*)g_A, i, c);
    float dv = g_dis[i];

    float row[8];
    row[4*c] = acc.x; row[4*c+1] = acc.y; row[4*c+2] = acc.z; row[4*c+3] = acc.w;
    {
        int cc = c ^ 1;
        row[4*cc]   = __shfl_xor_sync(0xffffffffu, acc.x, 1);
        row[4*cc+1] = __shfl_xor_sync(0xffffffffu, acc.y, 1);
        row[4*cc+2] = __shfl_xor_sync(0xffffffffu, acc.z, 1);
        row[4*cc+3] = __shfl_xor_sync(0xffffffffu, acc.w, 1);
    }

    float h3[16];
#pragma unroll
    for (int f = 0; f < 16; f++) h3[f] = sb3[f];
#pragma unroll
    for (int k = 0; k < 8; k++) {
        float a = dv * row[k];
#pragma unroll
        for (int f = 0; f < 16; f++) h3[f] = fmaf(a, sW3[k * 16 + f], h3[f]);
    }
#pragma unroll
    for (int f = 0; f < 16; f++) h3[f] = fmaxf(h3[f], 0.0f);

    float o[6];
#pragma unroll
    for (int f = 0; f < 6; f++) o[f] = 0.0f;
#pragma unroll
    for (int k = 0; k < 16; k++)
#pragma unroll
        for (int f = 0; f < 6; f++)
            o[f] = fmaf(h3[k], sW4[k * 12 + 6 * c + f], o[f]);

    float* op = g_B + (size_t)i * 16 + 6 * c;
#pragma unroll
    for (int f = 0; f < 6; f++) op[f] = o[f] * dv;
    if (c == 1) {   // pad cols 12..15
        float* pp = g_B + (size_t)i * 16 + 12;
        pp[0] = 0.0f; pp[1] = 0.0f; pp[2] = 0.0f; pp[3] = 0.0f;
    }
}

// ---- final: gather Y4 (B, 16-wide stride, 12 valid) -> sigmoid -> out -------
__global__ void final_kernel(float4* __restrict__ out, const float* __restrict__ b4) {
    int idx = blockIdx.x * blockDim.x + threadIdx.x;
    if (idx >= NN * 3) return;
    int i = idx / 3;
    int c = idx - i * 3;

    float4 acc = aggregate_chunk<4>((const float4*)g_B, i, c);   // stride 4, chunk c<3
    float dv = g_dis[i];

    float4 r;
    r.x = 1.0f / (1.0f + expf(-fmaf(dv, acc.x, b4[4 * c + 0])));
    r.y = 1.0f / (1.0f + expf(-fmaf(dv, acc.y, b4[4 * c + 1])));
    r.z = 1.0f / (1.0f + expf(-fmaf(dv, acc.z, b4[4 * c + 2])));
    r.w = 1.0f / (1.0f + expf(-fmaf(dv, acc.w, b4[4 * c + 3])));
    out[idx] = r;
}

// ---- launch -----------------------------------------------------------------
extern "C" void kernel_launch(void* const* d_in, const int* in_sizes, int n_in,
                              void* d_out, int out_size) {
    const float* x  = (const float*)d_in[0];
    const int*   ei = (const int*)d_in[1];   // int32 edge_index [2, E]
    const float* W1 = (const float*)d_in[2]; const float* b1 = (const float*)d_in[3];
    const float* W2 = (const float*)d_in[4]; const float* b2 = (const float*)d_in[5];
    const float* W3 = (const float*)d_in[6]; const float* b3 = (const float*)d_in[7];
    const float* W4 = (const float*)d_in[8]; const float* b4 = (const float*)d_in[9];
    float* out = (float*)d_out;

    const int BT = 256;
    const int gN = (NN + BT - 1) / BT;
    const int gE = (NE + BT - 1) / BT;
    const int g2 = (NN * 2 + BT - 1) / BT;
    const int g3 = (NN * 3 + BT - 1) / BT;
    const int g4 = (NN * 4 + BT - 1) / BT;

    zero_cnt_kernel<<<gN, BT>>>();
    count_deg_kernel<<<gE, BT>>>(ei);
    scan_kernel<<<NBLK, 1024>>>();           // rowptr/woff + dis, single pass
    fill_csr_kernel<<<gE, BT>>>(ei);
    lin1_pad_kernel<<<gN, BT>>>(x);          // pad tails + Y1 = dis*x -> A

    fused1_kernel<<<g4, BT>>>(W1, b1, W2);   // -> Y2 (B, 8)
    fused2_kernel<<<g2, BT>>>(b2);           // -> Y3 (A, 8)
    fused3_kernel<<<g2, BT>>>(W3, b3, W4);   // -> Y4 (B, 16 padded)
    final_kernel<<<g3, BT>>>((float4*)out, b4);
}